// round 12
// baseline (speedup 1.0000x reference)
#include <cuda_runtime.h>
#include <cuda_bf16.h>
#include <cuda_fp16.h>
#include <math.h>
#include <cstdint>

// Problem constants (fixed by setup_inputs)
#define PB 2
#define PT 2048
#define PC 2048
#define PH 16
#define PD 128
#define PM (PB*PT)        // 4096 rows of x
#define PHD (PH*PD)       // 2048

// ---------------- scratch (device globals; no allocs allowed) ----------------
__device__ float g_q[PB*PT*PH*PD];
__device__ float g_k[PB*PT*PH*PD];
__device__ float g_lf[PB*PH*PT];
__device__ float g_cf[PB*PH*PT];
__device__ __half g_vh[PB*PT*PH*PD]; // V, fp16 (written by QKV GEMM)
__device__ __half g_qh[PB*PT*PH*PD]; // rope+rms output, fp16, q pre-scaled
__device__ __half g_kh[PB*PT*PH*PD];
__device__ __half g_xh[PM*PC];       // x, fp16 (written by gate kernel)
__device__ __half g_yh[PM*PHD];      // attention output, fp16
__device__ __half g_wqh[PC*PHD];     // Wq^T [N,K], fp16
__device__ __half g_wkh[PC*PHD];
__device__ __half g_wvh[PC*PHD];
__device__ __half g_woh[PC*PC];

__device__ __forceinline__ void cp16s(unsigned saddr, const void* g) {
    asm volatile("cp.async.cg.shared.global [%0], [%1], 16;" :: "r"(saddr), "l"(g));
}

__device__ __forceinline__ void mma_f16(float* c, unsigned a0, unsigned a1,
                                        unsigned a2, unsigned a3,
                                        unsigned b0, unsigned b1) {
    asm volatile(
        "mma.sync.aligned.m16n8k16.row.col.f32.f16.f16.f32 "
        "{%0,%1,%2,%3}, {%4,%5,%6,%7}, {%8,%9}, {%0,%1,%2,%3};"
        : "+f"(c[0]), "+f"(c[1]), "+f"(c[2]), "+f"(c[3])
        : "r"(a0), "r"(a1), "r"(a2), "r"(a3), "r"(b0), "r"(b1));
}

__device__ __forceinline__ void ldsm_x4(unsigned& r0, unsigned& r1,
                                        unsigned& r2, unsigned& r3, unsigned sa) {
    asm volatile("ldmatrix.sync.aligned.m8n8.x4.shared.b16 {%0,%1,%2,%3}, [%4];"
                 : "=r"(r0), "=r"(r1), "=r"(r2), "=r"(r3) : "r"(sa));
}

__device__ __forceinline__ void ldsm_x4t(unsigned& r0, unsigned& r1,
                                         unsigned& r2, unsigned& r3, unsigned sa) {
    asm volatile("ldmatrix.sync.aligned.m8n8.x4.trans.shared.b16 {%0,%1,%2,%3}, [%4];"
                 : "=r"(r0), "=r"(r1), "=r"(r2), "=r"(r3) : "r"(sa));
}

// ================= fp16 tensor-core GEMM: C = A[M,K] @ Bt[N,K]^T =============
// CTA tile 128(M) x 256(N), BK=64, 512 threads (16 warps: 4M x 4N of 32x64),
// 3-stage cp.async ring, ldmatrix fragment loads.
#define ATILE_B (128*144)               // 18432 bytes (A: 128 rows x 144B)
#define GSTAGE  (ATILE_B + 256*144)     // 55296 bytes
#define HG_SMEM (3*GSTAGE)              // 165888

__device__ __forceinline__ void hgemm_body(const __half* __restrict__ A,
                                           const __half* __restrict__ Bt,
                                           float* __restrict__ Cf,
                                           __half* __restrict__ Ch,
                                           int M, int N, int K)
{
    extern __shared__ char smem[];
    unsigned sbase;
    asm("{ .reg .u64 t; cvta.to.shared.u64 t, %1; cvt.u32.u64 %0, t; }"
        : "=r"(sbase) : "l"(smem));

    const int tid = threadIdx.x;
    const int lane = tid & 31, warp = tid >> 5;
    const int g = lane >> 2, tg = lane & 3;
    const int wm = (warp & 3) * 32;
    const int wn = (warp >> 2) * 64;
    const int bm = blockIdx.y * 128, bn = blockIdx.x * 256;

    const unsigned aoff = (unsigned)(wm + (lane & 15)) * 144 + ((lane >> 4) << 4);
    const unsigned boff = (unsigned)(wn + (lane & 7) + ((lane >> 4) << 3)) * 144
                        + (((lane >> 3) & 1) << 4);

    float acc[2][8][4];
#pragma unroll
    for (int mt = 0; mt < 2; mt++)
#pragma unroll
        for (int nt = 0; nt < 8; nt++)
#pragma unroll
            for (int i = 0; i < 4; i++) acc[mt][nt][i] = 0.f;

    const int r0 = tid >> 3, cc = tid & 7;        // rows 0..63 (+64i), chunk 0..7
    const __half* Ag = A + (size_t)(bm + r0) * K + cc * 8;
    const __half* Bg = Bt + (size_t)(bn + r0) * K + cc * 8;
    const int nT = K / 64;

#define HLOAD(T, S)                                                             \
    {                                                                           \
        unsigned sa = sbase + (S) * GSTAGE + r0 * 144 + cc * 16;                \
        const __half* ga = Ag + (size_t)(T) * 64;                               \
        const __half* gb = Bg + (size_t)(T) * 64;                               \
        _Pragma("unroll")                                                       \
        for (int i = 0; i < 2; i++)                                             \
            cp16s(sa + i * (64 * 144), ga + (size_t)(64 * i) * K);              \
        _Pragma("unroll")                                                       \
        for (int i = 0; i < 4; i++)                                             \
            cp16s(sa + ATILE_B + i * (64 * 144), gb + (size_t)(64 * i) * K);    \
        asm volatile("cp.async.commit_group;");                                 \
    }

    HLOAD(0, 0);
    HLOAD(1, 1);

    int sid = 0, sid2 = 2;
    for (int t = 0; t < nT; t++) {
        if (t + 1 < nT) asm volatile("cp.async.wait_group 1;");
        else            asm volatile("cp.async.wait_group 0;");
        __syncthreads();
        if (t + 2 < nT) HLOAD(t + 2, sid2);

        const unsigned As = sbase + sid * GSTAGE;
        const unsigned Bs = As + ATILE_B;

#pragma unroll
        for (int kk = 0; kk < 4; kk++) {
            const unsigned kkb = kk << 5;
            unsigned a[2][4];
            ldsm_x4(a[0][0], a[0][1], a[0][2], a[0][3], As + aoff + kkb);
            ldsm_x4(a[1][0], a[1][1], a[1][2], a[1][3], As + aoff + 16 * 144 + kkb);
#pragma unroll
            for (int ntp = 0; ntp < 4; ntp++) {
                unsigned b0, b1, b2, b3;
                ldsm_x4(b0, b1, b2, b3, Bs + boff + ntp * (16 * 144) + kkb);
#pragma unroll
                for (int mt = 0; mt < 2; mt++) {
                    mma_f16(acc[mt][2 * ntp],     a[mt][0], a[mt][1], a[mt][2], a[mt][3], b0, b1);
                    mma_f16(acc[mt][2 * ntp + 1], a[mt][0], a[mt][1], a[mt][2], a[mt][3], b2, b3);
                }
            }
        }
        sid = (sid == 2) ? 0 : sid + 1;
        sid2 = (sid2 == 2) ? 0 : sid2 + 1;
    }
#undef HLOAD

    if (Ch) {
#pragma unroll
        for (int mt = 0; mt < 2; mt++)
#pragma unroll
            for (int nt = 0; nt < 8; nt++) {
                const int row0 = bm + wm + mt * 16 + g;
                const int col = bn + wn + nt * 8 + 2 * tg;
                __half2 h0 = __floats2half2_rn(acc[mt][nt][0], acc[mt][nt][1]);
                __half2 h1 = __floats2half2_rn(acc[mt][nt][2], acc[mt][nt][3]);
                *(unsigned*)&Ch[(size_t)row0 * N + col] = *(unsigned*)&h0;
                *(unsigned*)&Ch[(size_t)(row0 + 8) * N + col] = *(unsigned*)&h1;
            }
    } else {
#pragma unroll
        for (int mt = 0; mt < 2; mt++)
#pragma unroll
            for (int nt = 0; nt < 8; nt++) {
                const int row0 = bm + wm + mt * 16 + g;
                const int col = bn + wn + nt * 8 + 2 * tg;
                *(float2*)&Cf[(size_t)row0 * N + col] =
                    make_float2(acc[mt][nt][0], acc[mt][nt][1]);
                *(float2*)&Cf[(size_t)(row0 + 8) * N + col] =
                    make_float2(acc[mt][nt][2], acc[mt][nt][3]);
            }
    }
}

__global__ __launch_bounds__(512, 1) void hgemm(const __half* __restrict__ A,
                                                const __half* __restrict__ Bt,
                                                float* __restrict__ C,
                                                int M, int N, int K)
{
    hgemm_body(A, Bt, C, (__half*)0, M, N, K);
}

__global__ __launch_bounds__(512, 1) void hgemm_qkv(const __half* __restrict__ A,
                                                    const __half* __restrict__ B0,
                                                    const __half* __restrict__ B1,
                                                    const __half* __restrict__ B2,
                                                    float* __restrict__ C0,
                                                    float* __restrict__ C1,
                                                    __half* __restrict__ C2h,
                                                    int M, int N, int K)
{
    if (blockIdx.z == 0)      hgemm_body(A, B0, C0, (__half*)0, M, N, K);
    else if (blockIdx.z == 1) hgemm_body(A, B1, C1, (__half*)0, M, N, K);
    else                      hgemm_body(A, B2, (float*)0, C2h, M, N, K);
}

// ---------------- weight transpose + fp16: D[n][k] = h(W[k][n]) ----------------
__global__ __launch_bounds__(256) void wtrans_h(const float* __restrict__ s0,
                                                const float* __restrict__ s1,
                                                const float* __restrict__ s2,
                                                const float* __restrict__ s3,
                                                __half* __restrict__ d0,
                                                __half* __restrict__ d1,
                                                __half* __restrict__ d2,
                                                __half* __restrict__ d3)
{
    const int z = blockIdx.z;
    const float* S = (z == 0) ? s0 : (z == 1) ? s1 : (z == 2) ? s2 : s3;
    __half* D = (z == 0) ? d0 : (z == 1) ? d1 : (z == 2) ? d2 : d3;
    __shared__ float tile[32][33];
    const int tx = threadIdx.x & 31, ty = threadIdx.x >> 5;
    const int col = blockIdx.x * 32 + tx;
#pragma unroll
    for (int jj = 0; jj < 4; jj++)
        tile[ty + 8 * jj][tx] = S[(size_t)(blockIdx.y * 32 + ty + 8 * jj) * 2048 + col];
    __syncthreads();
    const int ocol = blockIdx.y * 32 + tx;
#pragma unroll
    for (int jj = 0; jj < 4; jj++)
        D[(size_t)(blockIdx.x * 32 + ty + 8 * jj) * 2048 + ocol] =
            __float2half_rn(tile[tx][ty + 8 * jj]);
}

// -------- gate kernel: 4 rows/block; also emits xh = fp16(x) (fused f2h) ------
__global__ __launch_bounds__(256) void gate_kernel(const float* __restrict__ x,
                                                   const float* __restrict__ fw,
                                                   const float* __restrict__ fb,
                                                   const float* __restrict__ wl,
                                                   float* __restrict__ lf,
                                                   __half* __restrict__ xh)
{
    __shared__ float xs[4][2048];
    __shared__ float4 red4[8][8][4];
    __shared__ float dots[4][32];
    const int bt0 = blockIdx.x * 4;
    const int tid = threadIdx.x;
    const int warp = tid >> 5, lane = tid & 31;
    const int grp = lane >> 2, koff = lane & 3;

#pragma unroll
    for (int i = 0; i < 8; i++) {
        int idx = tid + 256 * i;
        int row = idx >> 9, c4 = idx & 511;
        *(float4*)&xs[row][c4 * 4] =
            *(const float4*)&x[(size_t)(bt0 + row) * PC + c4 * 4];
    }
    __syncthreads();

    // fused fp16 conversion of x
#pragma unroll
    for (int i = 0; i < 8; i++) {
        int idx = tid + 256 * i;
        int row = idx >> 9, c4 = idx & 511;
        const float* p = &xs[row][c4 * 4];
        __half2 h0 = __floats2half2_rn(p[0], p[1]);
        __half2 h1 = __floats2half2_rn(p[2], p[3]);
        *(uint2*)&xh[(size_t)(bt0 + row) * PC + c4 * 4] =
            make_uint2(*(unsigned*)&h0, *(unsigned*)&h1);
    }

    const float* W = (grp < 4) ? fw : wl;
    const int h4 = (grp & 3) * 4;
    float4 s[4];
#pragma unroll
    for (int r = 0; r < 4; r++) s[r] = make_float4(0.f, 0.f, 0.f, 0.f);

    for (int i = 0; i < 64; i++) {
        int c = koff + 4 * warp + 32 * i;
        float4 wv = *(const float4*)&W[c * PH + h4];
#pragma unroll
        for (int r = 0; r < 4; r++) {
            float xv = xs[r][c];
            s[r].x += xv * wv.x; s[r].y += xv * wv.y;
            s[r].z += xv * wv.z; s[r].w += xv * wv.w;
        }
    }
#pragma unroll
    for (int off = 1; off < 4; off <<= 1) {
#pragma unroll
        for (int r = 0; r < 4; r++) {
            s[r].x += __shfl_xor_sync(0xffffffffu, s[r].x, off);
            s[r].y += __shfl_xor_sync(0xffffffffu, s[r].y, off);
            s[r].z += __shfl_xor_sync(0xffffffffu, s[r].z, off);
            s[r].w += __shfl_xor_sync(0xffffffffu, s[r].w, off);
        }
    }
    if (koff == 0) {
#pragma unroll
        for (int r = 0; r < 4; r++) red4[warp][grp][r] = s[r];
    }
    __syncthreads();
    if (tid < 128) {
        int row = tid >> 5, o = tid & 31;
        int gg = o >> 2, comp = o & 3;
        float t = 0.f;
#pragma unroll
        for (int w2 = 0; w2 < 8; w2++)
            t += ((const float*)&red4[w2][gg][row])[comp];
        dots[row][o] = t;
    }
    __syncthreads();
    if (tid < 64) {
        const int row = tid >> 4, hh = tid & 15;
        const int bt = bt0 + row;
        const int b = bt >> 11, t = bt & (PT - 1);
        float fdot = dots[row][hh] + fb[hh];
        float ldot = dots[row][16 + hh];
        float lam = ldot > 0.f ? ldot + 1.f : expf(ldot);
        float logit = fdot * lam;
        float ls = (logit >= 0.f) ? -log1pf(expf(-logit))
                                  : (logit - log1pf(expf(logit)));
        lf[((size_t)(b * PH + hh)) * PT + t] = ls / (lam + 0.001f);
    }
}

// ---------------- cumsum over T per (b,h) ----------------
__global__ __launch_bounds__(256) void cumsum_kernel(const float* __restrict__ lf,
                                                     float* __restrict__ cf)
{
    __shared__ float tot[256];
    const int bh = blockIdx.x, tid = threadIdx.x;
    const float* in = lf + (size_t)bh * PT;
    float* out = cf + (size_t)bh * PT;
    float v[8];
    float r = 0.f;
#pragma unroll
    for (int jj = 0; jj < 8; jj++) { r += in[tid * 8 + jj]; v[jj] = r; }
    tot[tid] = r;
    __syncthreads();
    for (int off = 1; off < 256; off <<= 1) {
        float t = 0.f;
        if (tid >= off) t = tot[tid - off];
        __syncthreads();
        if (tid >= off) tot[tid] += t;
        __syncthreads();
    }
    float base = tid ? tot[tid - 1] : 0.f;
#pragma unroll
    for (int jj = 0; jj < 8; jj++) out[tid * 8 + jj] = v[jj] + base;
}

// ---------- RoPE + RMSNorm: fp32 in, fp16 out (optionally pre-scaled) --------
__global__ __launch_bounds__(256) void rope_rms_h(const float* __restrict__ in,
                                                  __half* __restrict__ outh,
                                                  const float* __restrict__ cosp,
                                                  const float* __restrict__ sinp,
                                                  float scale)
{
    const int wid = blockIdx.x * 8 + (threadIdx.x >> 5);
    const int lane = threadIdx.x & 31;
    const int t = (wid >> 4) & (PT - 1);
    const float* row = in + (size_t)wid * PD;
    __half* orow = outh + (size_t)wid * PD;
    const int i0 = lane, i1 = lane + 32;
    float x1a = row[i0], x1b = row[i1];
    float x2a = row[i0 + 64], x2b = row[i1 + 64];
    float ca = cosp[t * 64 + i0], cb = cosp[t * 64 + i1];
    float sa = sinp[t * 64 + i0], sb = sinp[t * 64 + i1];
    float o0 = x1a * ca + x2a * sa;
    float o1 = x1b * cb + x2b * sb;
    float o2 = x2a * ca - x1a * sa;
    float o3 = x2b * cb - x1b * sb;
    float ss = o0 * o0 + o1 * o1 + o2 * o2 + o3 * o3;
#pragma unroll
    for (int off = 16; off > 0; off >>= 1) ss += __shfl_xor_sync(0xffffffffu, ss, off);
    float vv = ss * (1.f / 128.f) + 1.1920929e-07f;
    float inv = rsqrtf(vv);
    inv = inv * (1.5f - 0.5f * vv * inv * inv);
    inv *= scale;
    orow[i0] = __float2half_rn(o0 * inv);
    orow[i1] = __float2half_rn(o1 * inv);
    orow[i0 + 64] = __float2half_rn(o2 * inv);
    orow[i1 + 64] = __float2half_rn(o3 * inv);
}

// ---- windowed gated attention: all-fp16 mma, K/V double-buffered cp.async ----
#define SQ_OFF 0                        // 128 x 272B Q
#define SKV(buf) (34816 + (buf) * 34816)         // K then V per buffer
#define SK_OFF(buf) SKV(buf)
#define SV_OFF(buf) (SKV(buf) + 17408)
#define SC_OFF 104448                   // cfk[2][64] floats
#define AT_SMEM 104960

__global__ __launch_bounds__(256) void attn_mma_kernel(const __half* __restrict__ Qh,
                                                       const __half* __restrict__ Kh,
                                                       const __half* __restrict__ Vh,
                                                       const float* __restrict__ cumF,
                                                       __half* __restrict__ Yh,
                                                       const int* __restrict__ winp)
{
    extern __shared__ char sm8[];
    unsigned sb;
    asm("{ .reg .u64 t; cvta.to.shared.u64 t, %1; cvt.u32.u64 %0, t; }"
        : "=r"(sb) : "l"(sm8));
    float* cfk = (float*)(sm8 + SC_OFF);          // [2][64]

    const int tid = threadIdx.x;
    const int lane = tid & 31, warp = tid >> 5;
    const int g = lane >> 2, tg = lane & 3;
    const int wm = warp * 16;
    const int qt = blockIdx.x, h = blockIdx.y, b = blockIdx.z;
    const int q0 = qt * 128;
    const int win = *winp;
    const float* cF = cumF + (size_t)(b * PH + h) * PT;

    const unsigned qoff = (unsigned)(wm + (lane & 15)) * 272 + ((lane >> 4) << 4);
    const unsigned koff = (unsigned)((lane & 7) + ((lane >> 4) << 3)) * 272
                        + (((lane >> 3) & 1) << 4);
    const unsigned voff = (unsigned)((lane & 7) + (((lane >> 3) & 1) << 3)) * 272
                        + ((lane >> 4) << 4);

    const int kt_hi = (q0 + 127) >> 6;
    const int lo = q0 - win + 1;
    const int kt_min = lo > 0 ? (lo >> 6) : 0;

    // prologue: Q + KV(kt_hi) + cfk[0]
    {
        const __half* qg = Qh + ((size_t)(b * PT + q0) * PH + h) * PD;
#pragma unroll
        for (int i = 0; i < 8; i++) {
            int idx = tid + 256 * i;
            int r = idx >> 4, c = idx & 15;
            cp16s(sb + SQ_OFF + r * 272 + c * 16, qg + (size_t)r * PHD + c * 8);
        }
        const size_t base = ((size_t)(b * PT + kt_hi * 64) * PH + h) * PD;
#pragma unroll
        for (int i = 0; i < 4; i++) {
            int idx = tid + 256 * i;
            int r = idx >> 4, c = idx & 15;
            cp16s(sb + SK_OFF(0) + r * 272 + c * 16, Kh + base + (size_t)r * PHD + c * 8);
            cp16s(sb + SV_OFF(0) + r * 272 + c * 16, Vh + base + (size_t)r * PHD + c * 8);
        }
        asm volatile("cp.async.commit_group;");
        if (tid < 64) cfk[tid] = cF[kt_hi * 64 + tid];
    }

    const int rowA = wm + g, rowB = wm + g + 8;
    const float cfqA = cF[q0 + rowA];
    const float cfqB = cF[q0 + rowB];
    const int qiA = q0 + rowA, qiB = q0 + rowB;

    float mA = -1e30f, mB = -1e30f, lA = 0.f, lB = 0.f;
    float acc[16][4];
#pragma unroll
    for (int nt = 0; nt < 16; nt++)
#pragma unroll
        for (int i = 0; i < 4; i++) acc[nt][i] = 0.f;

    int it = 0;
    for (int kt = kt_hi; kt >= kt_min; --kt, ++it) {
        const int buf = it & 1;
        const int kb = kt * 64;
        asm volatile("cp.async.wait_group 0;");
        __syncthreads();

        // prefetch next tile into the other buffer
        if (kt - 1 >= kt_min) {
            const size_t base = ((size_t)(b * PT + kb - 64) * PH + h) * PD;
#pragma unroll
            for (int i = 0; i < 4; i++) {
                int idx = tid + 256 * i;
                int r = idx >> 4, c = idx & 15;
                cp16s(sb + SK_OFF(buf ^ 1) + r * 272 + c * 16,
                      Kh + base + (size_t)r * PHD + c * 8);
                cp16s(sb + SV_OFF(buf ^ 1) + r * 272 + c * 16,
                      Vh + base + (size_t)r * PHD + c * 8);
            }
            asm volatile("cp.async.commit_group;");
            if (tid < 64) cfk[(buf ^ 1) * 64 + tid] = cF[kb - 64 + tid];
        }

        // ---- S = Q K^T ----
        float sc_[8][4];
#pragma unroll
        for (int nt = 0; nt < 8; nt++)
#pragma unroll
            for (int i = 0; i < 4; i++) sc_[nt][i] = 0.f;

#pragma unroll
        for (int kk = 0; kk < 8; kk++) {
            const unsigned kkb = kk << 5;
            unsigned a0, a1, a2, a3;
            ldsm_x4(a0, a1, a2, a3, sb + SQ_OFF + qoff + kkb);
#pragma unroll
            for (int ntp = 0; ntp < 4; ntp++) {
                unsigned b0, b1, b2, b3;
                ldsm_x4(b0, b1, b2, b3, sb + SK_OFF(buf) + koff + ntp * (16 * 272) + kkb);
                mma_f16(sc_[2 * ntp],     a0, a1, a2, a3, b0, b1);
                mma_f16(sc_[2 * ntp + 1], a0, a1, a2, a3, b2, b3);
            }
        }

        // ---- bias + mask + online softmax (P packed to registers) ----
        const float* cfb = &cfk[buf * 64];
#pragma unroll
        for (int nt = 0; nt < 8; nt++) {
            const int j0 = kb + nt * 8 + 2 * tg;
            const int j1 = j0 + 1;
            const float c0 = cfb[nt * 8 + 2 * tg];
            const float c1 = cfb[nt * 8 + 2 * tg + 1];
            sc_[nt][0] = (j0 <= qiA && qiA - j0 < win) ? sc_[nt][0] + cfqA - c0 : -1e30f;
            sc_[nt][1] = (j1 <= qiA && qiA - j1 < win) ? sc_[nt][1] + cfqA - c1 : -1e30f;
            sc_[nt][2] = (j0 <= qiB && qiB - j0 < win) ? sc_[nt][2] + cfqB - c0 : -1e30f;
            sc_[nt][3] = (j1 <= qiB && qiB - j1 < win) ? sc_[nt][3] + cfqB - c1 : -1e30f;
        }
        float mxA = -1e30f, mxB = -1e30f;
#pragma unroll
        for (int nt = 0; nt < 8; nt++) {
            mxA = fmaxf(mxA, fmaxf(sc_[nt][0], sc_[nt][1]));
            mxB = fmaxf(mxB, fmaxf(sc_[nt][2], sc_[nt][3]));
        }
#pragma unroll
        for (int off = 1; off < 4; off <<= 1) {
            mxA = fmaxf(mxA, __shfl_xor_sync(0xffffffffu, mxA, off));
            mxB = fmaxf(mxB, __shfl_xor_sync(0xffffffffu, mxB, off));
        }
        const float mnA = fmaxf(mA, mxA);
        const float mnB = fmaxf(mB, mxB);
        const float scaA = __expf(mA - mnA);
        const float scaB = __expf(mB - mnB);
        mA = mnA; mB = mnB;

        float rsA = 0.f, rsB = 0.f;
        unsigned paA[8], paB[8];
#pragma unroll
        for (int nt = 0; nt < 8; nt++) {
            float p0 = (sc_[nt][0] > -1e29f) ? __expf(sc_[nt][0] - mnA) : 0.f;
            float p1 = (sc_[nt][1] > -1e29f) ? __expf(sc_[nt][1] - mnA) : 0.f;
            float p2 = (sc_[nt][2] > -1e29f) ? __expf(sc_[nt][2] - mnB) : 0.f;
            float p3 = (sc_[nt][3] > -1e29f) ? __expf(sc_[nt][3] - mnB) : 0.f;
            rsA += p0 + p1;
            rsB += p2 + p3;
            __half2 hA = __floats2half2_rn(p0, p1);
            __half2 hB = __floats2half2_rn(p2, p3);
            paA[nt] = *(unsigned*)&hA;
            paB[nt] = *(unsigned*)&hB;
        }
#pragma unroll
        for (int off = 1; off < 4; off <<= 1) {
            rsA += __shfl_xor_sync(0xffffffffu, rsA, off);
            rsB += __shfl_xor_sync(0xffffffffu, rsB, off);
        }
        lA = lA * scaA + rsA;
        lB = lB * scaB + rsB;
#pragma unroll
        for (int nt = 0; nt < 16; nt++) {
            acc[nt][0] *= scaA; acc[nt][1] *= scaA;
            acc[nt][2] *= scaB; acc[nt][3] *= scaB;
        }

        // ---- O += P V ----
#pragma unroll
        for (int j = 0; j < 4; j++) {
            const unsigned a0 = paA[2 * j], a1 = paB[2 * j];
            const unsigned a2 = paA[2 * j + 1], a3 = paB[2 * j + 1];
            const unsigned vrow = sb + SV_OFF(buf) + voff + j * (16 * 272);
#pragma unroll
            for (int ntp = 0; ntp < 8; ntp++) {
                unsigned b0, b1, b2, b3;
                ldsm_x4t(b0, b1, b2, b3, vrow + ntp * 32);
                mma_f16(acc[2 * ntp],     a0, a1, a2, a3, b0, b1);
                mma_f16(acc[2 * ntp + 1], a0, a1, a2, a3, b2, b3);
            }
        }
    }

    const float invA = 1.f / lA;
    const float invB = 1.f / lB;
#pragma unroll
    for (int nt = 0; nt < 16; nt++) {
        const int col = nt * 8 + 2 * tg;
        size_t oA = ((size_t)(b * PT + q0 + rowA) * PH + h) * PD + col;
        size_t oB = ((size_t)(b * PT + q0 + rowB) * PH + h) * PD + col;
        __half2 hA = __floats2half2_rn(acc[nt][0] * invA, acc[nt][1] * invA);
        __half2 hB = __floats2half2_rn(acc[nt][2] * invB, acc[nt][3] * invB);
        *(unsigned*)&Yh[oA] = *(unsigned*)&hA;
        *(unsigned*)&Yh[oB] = *(unsigned*)&hB;
    }
}

// ---------------- launch ----------------
extern "C" void kernel_launch(void* const* d_in, const int* in_sizes, int n_in,
                              void* d_out, int out_size)
{
    const float* x   = (const float*)d_in[0];
    const float* cosp= (const float*)d_in[1];
    const float* sinp= (const float*)d_in[2];
    const float* Wq  = (const float*)d_in[3];
    const float* Wk  = (const float*)d_in[4];
    const float* Wv  = (const float*)d_in[5];
    const float* Wo  = (const float*)d_in[6];
    const float* fw  = (const float*)d_in[7];
    const float* fb  = (const float*)d_in[8];
    const float* wl  = (const float*)d_in[9];
    const int*   win = (const int*)d_in[10];
    float* out = (float*)d_out;

    float *q, *k, *lf, *cf;
    __half *vh, *qh, *kh, *xh, *yh, *wqh, *wkh, *wvh, *woh;
    cudaGetSymbolAddress((void**)&q, g_q);
    cudaGetSymbolAddress((void**)&k, g_k);
    cudaGetSymbolAddress((void**)&lf, g_lf);
    cudaGetSymbolAddress((void**)&cf, g_cf);
    cudaGetSymbolAddress((void**)&vh, g_vh);
    cudaGetSymbolAddress((void**)&qh, g_qh);
    cudaGetSymbolAddress((void**)&kh, g_kh);
    cudaGetSymbolAddress((void**)&xh, g_xh);
    cudaGetSymbolAddress((void**)&yh, g_yh);
    cudaGetSymbolAddress((void**)&wqh, g_wqh);
    cudaGetSymbolAddress((void**)&wkh, g_wkh);
    cudaGetSymbolAddress((void**)&wvh, g_wvh);
    cudaGetSymbolAddress((void**)&woh, g_woh);

    cudaFuncSetAttribute(hgemm, cudaFuncAttributeMaxDynamicSharedMemorySize, HG_SMEM);
    cudaFuncSetAttribute(hgemm_qkv, cudaFuncAttributeMaxDynamicSharedMemorySize, HG_SMEM);
    cudaFuncSetAttribute(attn_mma_kernel, cudaFuncAttributeMaxDynamicSharedMemorySize, AT_SMEM);

    // gates (+ fused x->fp16)
    gate_kernel<<<PM / 4, 256>>>(x, fw, fb, wl, lf, xh);
    // weights -> transposed [N,K] fp16
    dim3 wt(64, 64, 4);
    wtrans_h<<<wt, 256>>>(Wq, Wk, Wv, Wo, wqh, wkh, wvh, woh);
    cumsum_kernel<<<PB * PH, 256>>>(lf, cf);
    // QKV GEMM (fp16 tensor cores, 128x256 CTA tiles); V written fp16
    dim3 gq(PHD / 256, PM / 128, 3);              // (8, 32, 3)
    hgemm_qkv<<<gq, 512, HG_SMEM>>>(xh, wqh, wkh, wvh, q, k, vh, PM, PHD, PC);
    // rope+rms -> fp16 (q pre-scaled by 1/sqrt(D))
    rope_rms_h<<<(PB * PT * PH) / 8, 256>>>(q, qh, cosp, sinp, 0.08838834764831845f);
    rope_rms_h<<<(PB * PT * PH) / 8, 256>>>(k, kh, cosp, sinp, 1.0f);
    // attention (all-fp16 mma, double-buffered K/V), writes fp16 Y
    dim3 ag(PT / 128, PH, PB);                    // (16, 16, 2)
    attn_mma_kernel<<<ag, 256, AT_SMEM>>>(qh, kh, vh, cf, yh, win);
    // Wo GEMM (fp16 in, fp32 out)
    dim3 gg(PC / 256, PM / 128);                  // (8, 32)
    hgemm<<<gg, 512, HG_SMEM>>>(yh, woh, out, PM, PC, PC);
}

// round 13
// speedup vs baseline: 1.0960x; 1.0960x over previous
#include <cuda_runtime.h>
#include <cuda_bf16.h>
#include <cuda_fp16.h>
#include <math.h>
#include <cstdint>

// Problem constants (fixed by setup_inputs)
#define PB 2
#define PT 2048
#define PC 2048
#define PH 16
#define PD 128
#define PM (PB*PT)        // 4096 rows of x
#define PHD (PH*PD)       // 2048

// ---------------- scratch (device globals; no allocs allowed) ----------------
__device__ float g_q[PB*PT*PH*PD];
__device__ float g_k[PB*PT*PH*PD];
__device__ float g_lf[PB*PH*PT];
__device__ float g_cf[PB*PH*PT];
__device__ __half g_vh[PB*PT*PH*PD]; // V, fp16 (written by QKV GEMM)
__device__ __half g_qh[PB*PT*PH*PD]; // rope+rms output, fp16, q pre-scaled
__device__ __half g_kh[PB*PT*PH*PD];
__device__ __half g_xh[PM*PC];       // x, fp16 (written by gate kernel)
__device__ __half g_yh[PM*PHD];      // attention output, fp16
__device__ __half g_wqh[PC*PHD];     // Wq^T [N,K], fp16
__device__ __half g_wkh[PC*PHD];
__device__ __half g_wvh[PC*PHD];
__device__ __half g_woh[PC*PC];

__device__ __forceinline__ void cp16s(unsigned saddr, const void* g) {
    asm volatile("cp.async.cg.shared.global [%0], [%1], 16;" :: "r"(saddr), "l"(g));
}

__device__ __forceinline__ void mma_f16(float* c, unsigned a0, unsigned a1,
                                        unsigned a2, unsigned a3,
                                        unsigned b0, unsigned b1) {
    asm volatile(
        "mma.sync.aligned.m16n8k16.row.col.f32.f16.f16.f32 "
        "{%0,%1,%2,%3}, {%4,%5,%6,%7}, {%8,%9}, {%0,%1,%2,%3};"
        : "+f"(c[0]), "+f"(c[1]), "+f"(c[2]), "+f"(c[3])
        : "r"(a0), "r"(a1), "r"(a2), "r"(a3), "r"(b0), "r"(b1));
}

__device__ __forceinline__ void ldsm_x4(unsigned& r0, unsigned& r1,
                                        unsigned& r2, unsigned& r3, unsigned sa) {
    asm volatile("ldmatrix.sync.aligned.m8n8.x4.shared.b16 {%0,%1,%2,%3}, [%4];"
                 : "=r"(r0), "=r"(r1), "=r"(r2), "=r"(r3) : "r"(sa));
}

__device__ __forceinline__ void ldsm_x4t(unsigned& r0, unsigned& r1,
                                         unsigned& r2, unsigned& r3, unsigned sa) {
    asm volatile("ldmatrix.sync.aligned.m8n8.x4.trans.shared.b16 {%0,%1,%2,%3}, [%4];"
                 : "=r"(r0), "=r"(r1), "=r"(r2), "=r"(r3) : "r"(sa));
}

// ================= fp16 tensor-core GEMM: C = A[M,K] @ Bt[N,K]^T =============
// R11 config: 128x128x64 CTA tiles, 256 threads (8 warps: 4M x 2N of 32x64),
// 3-stage cp.async ring, ldmatrix fragment loads, 2 CTAs/SM.
#define HS 72                           // smem row stride in halfs (144 bytes)
#define HTILE (128*HS*2)                // 18432 B per operand tile
#define HSTAGE (2*HTILE)                // 36864
#define HG_SMEM (3*HSTAGE)              // 110592

__device__ __forceinline__ void hgemm_body(const __half* __restrict__ A,
                                           const __half* __restrict__ Bt,
                                           float* __restrict__ Cf,
                                           __half* __restrict__ Ch,
                                           int M, int N, int K)
{
    extern __shared__ char smem[];
    unsigned sbase;
    asm("{ .reg .u64 t; cvta.to.shared.u64 t, %1; cvt.u32.u64 %0, t; }"
        : "=r"(sbase) : "l"(smem));

    const int tid = threadIdx.x;
    const int lane = tid & 31, warp = tid >> 5;
    const int g = lane >> 2, tg = lane & 3;
    const int wm = (warp & 3) * 32;
    const int wn = (warp >> 2) * 64;
    const int bm = blockIdx.y * 128, bn = blockIdx.x * 128;

    const unsigned aoff = (unsigned)(wm + (lane & 15)) * 144 + ((lane >> 4) << 4);
    const unsigned boff = (unsigned)(wn + (lane & 7) + ((lane >> 4) << 3)) * 144
                        + (((lane >> 3) & 1) << 4);

    float acc[2][8][4];
#pragma unroll
    for (int mt = 0; mt < 2; mt++)
#pragma unroll
        for (int nt = 0; nt < 8; nt++)
#pragma unroll
            for (int i = 0; i < 4; i++) acc[mt][nt][i] = 0.f;

    const int r0 = tid >> 3, cc = tid & 7;
    const __half* Ag = A + (size_t)(bm + r0) * K + cc * 8;
    const __half* Bg = Bt + (size_t)(bn + r0) * K + cc * 8;
    const int nT = K / 64;

#define HLOAD(T, S)                                                             \
    {                                                                           \
        unsigned sa = sbase + (S) * HSTAGE + r0 * 144 + cc * 16;                \
        const __half* ga = Ag + (size_t)(T) * 64;                               \
        const __half* gb = Bg + (size_t)(T) * 64;                               \
        _Pragma("unroll")                                                       \
        for (int i = 0; i < 4; i++) {                                           \
            cp16s(sa + i * (32 * 144),         ga + (size_t)(32 * i) * K);      \
            cp16s(sa + HTILE + i * (32 * 144), gb + (size_t)(32 * i) * K);      \
        }                                                                       \
        asm volatile("cp.async.commit_group;");                                 \
    }

    HLOAD(0, 0);
    HLOAD(1, 1);

    int sid = 0, sid2 = 2;
    for (int t = 0; t < nT; t++) {
        if (t + 1 < nT) asm volatile("cp.async.wait_group 1;");
        else            asm volatile("cp.async.wait_group 0;");
        __syncthreads();
        if (t + 2 < nT) HLOAD(t + 2, sid2);

        const unsigned As = sbase + sid * HSTAGE;
        const unsigned Bs = As + HTILE;

#pragma unroll
        for (int kk = 0; kk < 4; kk++) {
            const unsigned kkb = kk << 5;
            unsigned a[2][4];
            ldsm_x4(a[0][0], a[0][1], a[0][2], a[0][3], As + aoff + kkb);
            ldsm_x4(a[1][0], a[1][1], a[1][2], a[1][3], As + aoff + 16 * 144 + kkb);
#pragma unroll
            for (int ntp = 0; ntp < 4; ntp++) {
                unsigned b0, b1, b2, b3;
                ldsm_x4(b0, b1, b2, b3, Bs + boff + ntp * (16 * 144) + kkb);
#pragma unroll
                for (int mt = 0; mt < 2; mt++) {
                    mma_f16(acc[mt][2 * ntp],     a[mt][0], a[mt][1], a[mt][2], a[mt][3], b0, b1);
                    mma_f16(acc[mt][2 * ntp + 1], a[mt][0], a[mt][1], a[mt][2], a[mt][3], b2, b3);
                }
            }
        }
        sid = (sid == 2) ? 0 : sid + 1;
        sid2 = (sid2 == 2) ? 0 : sid2 + 1;
    }
#undef HLOAD

    if (Ch) {
#pragma unroll
        for (int mt = 0; mt < 2; mt++)
#pragma unroll
            for (int nt = 0; nt < 8; nt++) {
                const int row0 = bm + wm + mt * 16 + g;
                const int col = bn + wn + nt * 8 + 2 * tg;
                __half2 h0 = __floats2half2_rn(acc[mt][nt][0], acc[mt][nt][1]);
                __half2 h1 = __floats2half2_rn(acc[mt][nt][2], acc[mt][nt][3]);
                *(unsigned*)&Ch[(size_t)row0 * N + col] = *(unsigned*)&h0;
                *(unsigned*)&Ch[(size_t)(row0 + 8) * N + col] = *(unsigned*)&h1;
            }
    } else {
#pragma unroll
        for (int mt = 0; mt < 2; mt++)
#pragma unroll
            for (int nt = 0; nt < 8; nt++) {
                const int row0 = bm + wm + mt * 16 + g;
                const int col = bn + wn + nt * 8 + 2 * tg;
                *(float2*)&Cf[(size_t)row0 * N + col] =
                    make_float2(acc[mt][nt][0], acc[mt][nt][1]);
                *(float2*)&Cf[(size_t)(row0 + 8) * N + col] =
                    make_float2(acc[mt][nt][2], acc[mt][nt][3]);
            }
    }
}

__global__ __launch_bounds__(256, 2) void hgemm(const __half* __restrict__ A,
                                                const __half* __restrict__ Bt,
                                                float* __restrict__ C,
                                                int M, int N, int K)
{
    hgemm_body(A, Bt, C, (__half*)0, M, N, K);
}

__global__ __launch_bounds__(256, 2) void hgemm_qkv(const __half* __restrict__ A,
                                                    const __half* __restrict__ B0,
                                                    const __half* __restrict__ B1,
                                                    const __half* __restrict__ B2,
                                                    float* __restrict__ C0,
                                                    float* __restrict__ C1,
                                                    __half* __restrict__ C2h,
                                                    int M, int N, int K)
{
    if (blockIdx.z == 0)      hgemm_body(A, B0, C0, (__half*)0, M, N, K);
    else if (blockIdx.z == 1) hgemm_body(A, B1, C1, (__half*)0, M, N, K);
    else                      hgemm_body(A, B2, (float*)0, C2h, M, N, K);
}

// ---------------- weight transpose + fp16: D[n][k] = h(W[k][n]) ----------------
__global__ __launch_bounds__(256) void wtrans_h(const float* __restrict__ s0,
                                                const float* __restrict__ s1,
                                                const float* __restrict__ s2,
                                                const float* __restrict__ s3,
                                                __half* __restrict__ d0,
                                                __half* __restrict__ d1,
                                                __half* __restrict__ d2,
                                                __half* __restrict__ d3)
{
    const int z = blockIdx.z;
    const float* S = (z == 0) ? s0 : (z == 1) ? s1 : (z == 2) ? s2 : s3;
    __half* D = (z == 0) ? d0 : (z == 1) ? d1 : (z == 2) ? d2 : d3;
    __shared__ float tile[32][33];
    const int tx = threadIdx.x & 31, ty = threadIdx.x >> 5;
    const int col = blockIdx.x * 32 + tx;
#pragma unroll
    for (int jj = 0; jj < 4; jj++)
        tile[ty + 8 * jj][tx] = S[(size_t)(blockIdx.y * 32 + ty + 8 * jj) * 2048 + col];
    __syncthreads();
    const int ocol = blockIdx.y * 32 + tx;
#pragma unroll
    for (int jj = 0; jj < 4; jj++)
        D[(size_t)(blockIdx.x * 32 + ty + 8 * jj) * 2048 + ocol] =
            __float2half_rn(tile[tx][ty + 8 * jj]);
}

// -------- gate kernel: 4 rows/block; also emits xh = fp16(x) (fused f2h) ------
__global__ __launch_bounds__(256) void gate_kernel(const float* __restrict__ x,
                                                   const float* __restrict__ fw,
                                                   const float* __restrict__ fb,
                                                   const float* __restrict__ wl,
                                                   float* __restrict__ lf,
                                                   __half* __restrict__ xh)
{
    __shared__ float xs[4][2048];
    __shared__ float4 red4[8][8][4];
    __shared__ float dots[4][32];
    const int bt0 = blockIdx.x * 4;
    const int tid = threadIdx.x;
    const int warp = tid >> 5, lane = tid & 31;
    const int grp = lane >> 2, koff = lane & 3;

#pragma unroll
    for (int i = 0; i < 8; i++) {
        int idx = tid + 256 * i;
        int row = idx >> 9, c4 = idx & 511;
        *(float4*)&xs[row][c4 * 4] =
            *(const float4*)&x[(size_t)(bt0 + row) * PC + c4 * 4];
    }
    __syncthreads();

    // fused fp16 conversion of x
#pragma unroll
    for (int i = 0; i < 8; i++) {
        int idx = tid + 256 * i;
        int row = idx >> 9, c4 = idx & 511;
        const float* p = &xs[row][c4 * 4];
        __half2 h0 = __floats2half2_rn(p[0], p[1]);
        __half2 h1 = __floats2half2_rn(p[2], p[3]);
        *(uint2*)&xh[(size_t)(bt0 + row) * PC + c4 * 4] =
            make_uint2(*(unsigned*)&h0, *(unsigned*)&h1);
    }

    const float* W = (grp < 4) ? fw : wl;
    const int h4 = (grp & 3) * 4;
    float4 s[4];
#pragma unroll
    for (int r = 0; r < 4; r++) s[r] = make_float4(0.f, 0.f, 0.f, 0.f);

    for (int i = 0; i < 64; i++) {
        int c = koff + 4 * warp + 32 * i;
        float4 wv = *(const float4*)&W[c * PH + h4];
#pragma unroll
        for (int r = 0; r < 4; r++) {
            float xv = xs[r][c];
            s[r].x += xv * wv.x; s[r].y += xv * wv.y;
            s[r].z += xv * wv.z; s[r].w += xv * wv.w;
        }
    }
#pragma unroll
    for (int off = 1; off < 4; off <<= 1) {
#pragma unroll
        for (int r = 0; r < 4; r++) {
            s[r].x += __shfl_xor_sync(0xffffffffu, s[r].x, off);
            s[r].y += __shfl_xor_sync(0xffffffffu, s[r].y, off);
            s[r].z += __shfl_xor_sync(0xffffffffu, s[r].z, off);
            s[r].w += __shfl_xor_sync(0xffffffffu, s[r].w, off);
        }
    }
    if (koff == 0) {
#pragma unroll
        for (int r = 0; r < 4; r++) red4[warp][grp][r] = s[r];
    }
    __syncthreads();
    if (tid < 128) {
        int row = tid >> 5, o = tid & 31;
        int gg = o >> 2, comp = o & 3;
        float t = 0.f;
#pragma unroll
        for (int w2 = 0; w2 < 8; w2++)
            t += ((const float*)&red4[w2][gg][row])[comp];
        dots[row][o] = t;
    }
    __syncthreads();
    if (tid < 64) {
        const int row = tid >> 4, hh = tid & 15;
        const int bt = bt0 + row;
        const int b = bt >> 11, t = bt & (PT - 1);
        float fdot = dots[row][hh] + fb[hh];
        float ldot = dots[row][16 + hh];
        float lam = ldot > 0.f ? ldot + 1.f : expf(ldot);
        float logit = fdot * lam;
        float ls = (logit >= 0.f) ? -log1pf(expf(-logit))
                                  : (logit - log1pf(expf(logit)));
        lf[((size_t)(b * PH + hh)) * PT + t] = ls / (lam + 0.001f);
    }
}

// ---------------- cumsum over T per (b,h) ----------------
__global__ __launch_bounds__(256) void cumsum_kernel(const float* __restrict__ lf,
                                                     float* __restrict__ cf)
{
    __shared__ float tot[256];
    const int bh = blockIdx.x, tid = threadIdx.x;
    const float* in = lf + (size_t)bh * PT;
    float* out = cf + (size_t)bh * PT;
    float v[8];
    float r = 0.f;
#pragma unroll
    for (int jj = 0; jj < 8; jj++) { r += in[tid * 8 + jj]; v[jj] = r; }
    tot[tid] = r;
    __syncthreads();
    for (int off = 1; off < 256; off <<= 1) {
        float t = 0.f;
        if (tid >= off) t = tot[tid - off];
        __syncthreads();
        if (tid >= off) tot[tid] += t;
        __syncthreads();
    }
    float base = tid ? tot[tid - 1] : 0.f;
#pragma unroll
    for (int jj = 0; jj < 8; jj++) out[tid * 8 + jj] = v[jj] + base;
}

// ---------- RoPE + RMSNorm: fp32 in, fp16 out (optionally pre-scaled) --------
__global__ __launch_bounds__(256) void rope_rms_h(const float* __restrict__ in,
                                                  __half* __restrict__ outh,
                                                  const float* __restrict__ cosp,
                                                  const float* __restrict__ sinp,
                                                  float scale)
{
    const int wid = blockIdx.x * 8 + (threadIdx.x >> 5);
    const int lane = threadIdx.x & 31;
    const int t = (wid >> 4) & (PT - 1);
    const float* row = in + (size_t)wid * PD;
    __half* orow = outh + (size_t)wid * PD;
    const int i0 = lane, i1 = lane + 32;
    float x1a = row[i0], x1b = row[i1];
    float x2a = row[i0 + 64], x2b = row[i1 + 64];
    float ca = cosp[t * 64 + i0], cb = cosp[t * 64 + i1];
    float sa = sinp[t * 64 + i0], sb = sinp[t * 64 + i1];
    float o0 = x1a * ca + x2a * sa;
    float o1 = x1b * cb + x2b * sb;
    float o2 = x2a * ca - x1a * sa;
    float o3 = x2b * cb - x1b * sb;
    float ss = o0 * o0 + o1 * o1 + o2 * o2 + o3 * o3;
#pragma unroll
    for (int off = 16; off > 0; off >>= 1) ss += __shfl_xor_sync(0xffffffffu, ss, off);
    float vv = ss * (1.f / 128.f) + 1.1920929e-07f;
    float inv = rsqrtf(vv);
    inv = inv * (1.5f - 0.5f * vv * inv * inv);
    inv *= scale;
    orow[i0] = __float2half_rn(o0 * inv);
    orow[i1] = __float2half_rn(o1 * inv);
    orow[i0 + 64] = __float2half_rn(o2 * inv);
    orow[i1 + 64] = __float2half_rn(o3 * inv);
}

// ---- windowed gated attention: all-fp16 mma, K/V double-buffered cp.async ----
#define SQ_OFF 0                        // 128 x 272B Q
#define SKV(buf) (34816 + (buf) * 34816)         // K then V per buffer
#define SK_OFF(buf) SKV(buf)
#define SV_OFF(buf) (SKV(buf) + 17408)
#define SC_OFF 104448                   // cfk[2][64] floats
#define AT_SMEM 104960

__global__ __launch_bounds__(256) void attn_mma_kernel(const __half* __restrict__ Qh,
                                                       const __half* __restrict__ Kh,
                                                       const __half* __restrict__ Vh,
                                                       const float* __restrict__ cumF,
                                                       __half* __restrict__ Yh,
                                                       const int* __restrict__ winp)
{
    extern __shared__ char sm8[];
    unsigned sb;
    asm("{ .reg .u64 t; cvta.to.shared.u64 t, %1; cvt.u32.u64 %0, t; }"
        : "=r"(sb) : "l"(sm8));
    float* cfk = (float*)(sm8 + SC_OFF);          // [2][64]

    const int tid = threadIdx.x;
    const int lane = tid & 31, warp = tid >> 5;
    const int g = lane >> 2, tg = lane & 3;
    const int wm = warp * 16;
    const int qt = blockIdx.x, h = blockIdx.y, b = blockIdx.z;
    const int q0 = qt * 128;
    const int win = *winp;
    const float* cF = cumF + (size_t)(b * PH + h) * PT;

    const unsigned qoff = (unsigned)(wm + (lane & 15)) * 272 + ((lane >> 4) << 4);
    const unsigned koff = (unsigned)((lane & 7) + ((lane >> 4) << 3)) * 272
                        + (((lane >> 3) & 1) << 4);
    const unsigned voff = (unsigned)((lane & 7) + (((lane >> 3) & 1) << 3)) * 272
                        + ((lane >> 4) << 4);

    const int kt_hi = (q0 + 127) >> 6;
    const int lo = q0 - win + 1;
    const int kt_min = lo > 0 ? (lo >> 6) : 0;

    // prologue: Q + KV(kt_hi) + cfk[0]
    {
        const __half* qg = Qh + ((size_t)(b * PT + q0) * PH + h) * PD;
#pragma unroll
        for (int i = 0; i < 8; i++) {
            int idx = tid + 256 * i;
            int r = idx >> 4, c = idx & 15;
            cp16s(sb + SQ_OFF + r * 272 + c * 16, qg + (size_t)r * PHD + c * 8);
        }
        const size_t base = ((size_t)(b * PT + kt_hi * 64) * PH + h) * PD;
#pragma unroll
        for (int i = 0; i < 4; i++) {
            int idx = tid + 256 * i;
            int r = idx >> 4, c = idx & 15;
            cp16s(sb + SK_OFF(0) + r * 272 + c * 16, Kh + base + (size_t)r * PHD + c * 8);
            cp16s(sb + SV_OFF(0) + r * 272 + c * 16, Vh + base + (size_t)r * PHD + c * 8);
        }
        asm volatile("cp.async.commit_group;");
        if (tid < 64) cfk[tid] = cF[kt_hi * 64 + tid];
    }

    const int rowA = wm + g, rowB = wm + g + 8;
    const float cfqA = cF[q0 + rowA];
    const float cfqB = cF[q0 + rowB];
    const int qiA = q0 + rowA, qiB = q0 + rowB;

    float mA = -1e30f, mB = -1e30f, lA = 0.f, lB = 0.f;
    float acc[16][4];
#pragma unroll
    for (int nt = 0; nt < 16; nt++)
#pragma unroll
        for (int i = 0; i < 4; i++) acc[nt][i] = 0.f;

    int it = 0;
    for (int kt = kt_hi; kt >= kt_min; --kt, ++it) {
        const int buf = it & 1;
        const int kb = kt * 64;
        asm volatile("cp.async.wait_group 0;");
        __syncthreads();

        // prefetch next tile into the other buffer
        if (kt - 1 >= kt_min) {
            const size_t base = ((size_t)(b * PT + kb - 64) * PH + h) * PD;
#pragma unroll
            for (int i = 0; i < 4; i++) {
                int idx = tid + 256 * i;
                int r = idx >> 4, c = idx & 15;
                cp16s(sb + SK_OFF(buf ^ 1) + r * 272 + c * 16,
                      Kh + base + (size_t)r * PHD + c * 8);
                cp16s(sb + SV_OFF(buf ^ 1) + r * 272 + c * 16,
                      Vh + base + (size_t)r * PHD + c * 8);
            }
            asm volatile("cp.async.commit_group;");
            if (tid < 64) cfk[(buf ^ 1) * 64 + tid] = cF[kb - 64 + tid];
        }

        // ---- S = Q K^T ----
        float sc_[8][4];
#pragma unroll
        for (int nt = 0; nt < 8; nt++)
#pragma unroll
            for (int i = 0; i < 4; i++) sc_[nt][i] = 0.f;

#pragma unroll
        for (int kk = 0; kk < 8; kk++) {
            const unsigned kkb = kk << 5;
            unsigned a0, a1, a2, a3;
            ldsm_x4(a0, a1, a2, a3, sb + SQ_OFF + qoff + kkb);
#pragma unroll
            for (int ntp = 0; ntp < 4; ntp++) {
                unsigned b0, b1, b2, b3;
                ldsm_x4(b0, b1, b2, b3, sb + SK_OFF(buf) + koff + ntp * (16 * 272) + kkb);
                mma_f16(sc_[2 * ntp],     a0, a1, a2, a3, b0, b1);
                mma_f16(sc_[2 * ntp + 1], a0, a1, a2, a3, b2, b3);
            }
        }

        // ---- bias + mask + online softmax (P packed to registers) ----
        const float* cfb = &cfk[buf * 64];
#pragma unroll
        for (int nt = 0; nt < 8; nt++) {
            const int j0 = kb + nt * 8 + 2 * tg;
            const int j1 = j0 + 1;
            const float c0 = cfb[nt * 8 + 2 * tg];
            const float c1 = cfb[nt * 8 + 2 * tg + 1];
            sc_[nt][0] = (j0 <= qiA && qiA - j0 < win) ? sc_[nt][0] + cfqA - c0 : -1e30f;
            sc_[nt][1] = (j1 <= qiA && qiA - j1 < win) ? sc_[nt][1] + cfqA - c1 : -1e30f;
            sc_[nt][2] = (j0 <= qiB && qiB - j0 < win) ? sc_[nt][2] + cfqB - c0 : -1e30f;
            sc_[nt][3] = (j1 <= qiB && qiB - j1 < win) ? sc_[nt][3] + cfqB - c1 : -1e30f;
        }
        float mxA = -1e30f, mxB = -1e30f;
#pragma unroll
        for (int nt = 0; nt < 8; nt++) {
            mxA = fmaxf(mxA, fmaxf(sc_[nt][0], sc_[nt][1]));
            mxB = fmaxf(mxB, fmaxf(sc_[nt][2], sc_[nt][3]));
        }
#pragma unroll
        for (int off = 1; off < 4; off <<= 1) {
            mxA = fmaxf(mxA, __shfl_xor_sync(0xffffffffu, mxA, off));
            mxB = fmaxf(mxB, __shfl_xor_sync(0xffffffffu, mxB, off));
        }
        const float mnA = fmaxf(mA, mxA);
        const float mnB = fmaxf(mB, mxB);
        const float scaA = __expf(mA - mnA);
        const float scaB = __expf(mB - mnB);
        mA = mnA; mB = mnB;

        float rsA = 0.f, rsB = 0.f;
        unsigned paA[8], paB[8];
#pragma unroll
        for (int nt = 0; nt < 8; nt++) {
            float p0 = (sc_[nt][0] > -1e29f) ? __expf(sc_[nt][0] - mnA) : 0.f;
            float p1 = (sc_[nt][1] > -1e29f) ? __expf(sc_[nt][1] - mnA) : 0.f;
            float p2 = (sc_[nt][2] > -1e29f) ? __expf(sc_[nt][2] - mnB) : 0.f;
            float p3 = (sc_[nt][3] > -1e29f) ? __expf(sc_[nt][3] - mnB) : 0.f;
            rsA += p0 + p1;
            rsB += p2 + p3;
            __half2 hA = __floats2half2_rn(p0, p1);
            __half2 hB = __floats2half2_rn(p2, p3);
            paA[nt] = *(unsigned*)&hA;
            paB[nt] = *(unsigned*)&hB;
        }
#pragma unroll
        for (int off = 1; off < 4; off <<= 1) {
            rsA += __shfl_xor_sync(0xffffffffu, rsA, off);
            rsB += __shfl_xor_sync(0xffffffffu, rsB, off);
        }
        lA = lA * scaA + rsA;
        lB = lB * scaB + rsB;
#pragma unroll
        for (int nt = 0; nt < 16; nt++) {
            acc[nt][0] *= scaA; acc[nt][1] *= scaA;
            acc[nt][2] *= scaB; acc[nt][3] *= scaB;
        }

        // ---- O += P V ----
#pragma unroll
        for (int j = 0; j < 4; j++) {
            const unsigned a0 = paA[2 * j], a1 = paB[2 * j];
            const unsigned a2 = paA[2 * j + 1], a3 = paB[2 * j + 1];
            const unsigned vrow = sb + SV_OFF(buf) + voff + j * (16 * 272);
#pragma unroll
            for (int ntp = 0; ntp < 8; ntp++) {
                unsigned b0, b1, b2, b3;
                ldsm_x4t(b0, b1, b2, b3, vrow + ntp * 32);
                mma_f16(acc[2 * ntp],     a0, a1, a2, a3, b0, b1);
                mma_f16(acc[2 * ntp + 1], a0, a1, a2, a3, b2, b3);
            }
        }
    }

    const float invA = 1.f / lA;
    const float invB = 1.f / lB;
#pragma unroll
    for (int nt = 0; nt < 16; nt++) {
        const int col = nt * 8 + 2 * tg;
        size_t oA = ((size_t)(b * PT + q0 + rowA) * PH + h) * PD + col;
        size_t oB = ((size_t)(b * PT + q0 + rowB) * PH + h) * PD + col;
        __half2 hA = __floats2half2_rn(acc[nt][0] * invA, acc[nt][1] * invA);
        __half2 hB = __floats2half2_rn(acc[nt][2] * invB, acc[nt][3] * invB);
        *(unsigned*)&Yh[oA] = *(unsigned*)&hA;
        *(unsigned*)&Yh[oB] = *(unsigned*)&hB;
    }
}

// ---------------- launch ----------------
extern "C" void kernel_launch(void* const* d_in, const int* in_sizes, int n_in,
                              void* d_out, int out_size)
{
    const float* x   = (const float*)d_in[0];
    const float* cosp= (const float*)d_in[1];
    const float* sinp= (const float*)d_in[2];
    const float* Wq  = (const float*)d_in[3];
    const float* Wk  = (const float*)d_in[4];
    const float* Wv  = (const float*)d_in[5];
    const float* Wo  = (const float*)d_in[6];
    const float* fw  = (const float*)d_in[7];
    const float* fb  = (const float*)d_in[8];
    const float* wl  = (const float*)d_in[9];
    const int*   win = (const int*)d_in[10];
    float* out = (float*)d_out;

    float *q, *k, *lf, *cf;
    __half *vh, *qh, *kh, *xh, *yh, *wqh, *wkh, *wvh, *woh;
    cudaGetSymbolAddress((void**)&q, g_q);
    cudaGetSymbolAddress((void**)&k, g_k);
    cudaGetSymbolAddress((void**)&lf, g_lf);
    cudaGetSymbolAddress((void**)&cf, g_cf);
    cudaGetSymbolAddress((void**)&vh, g_vh);
    cudaGetSymbolAddress((void**)&qh, g_qh);
    cudaGetSymbolAddress((void**)&kh, g_kh);
    cudaGetSymbolAddress((void**)&xh, g_xh);
    cudaGetSymbolAddress((void**)&yh, g_yh);
    cudaGetSymbolAddress((void**)&wqh, g_wqh);
    cudaGetSymbolAddress((void**)&wkh, g_wkh);
    cudaGetSymbolAddress((void**)&wvh, g_wvh);
    cudaGetSymbolAddress((void**)&woh, g_woh);

    cudaFuncSetAttribute(hgemm, cudaFuncAttributeMaxDynamicSharedMemorySize, HG_SMEM);
    cudaFuncSetAttribute(hgemm_qkv, cudaFuncAttributeMaxDynamicSharedMemorySize, HG_SMEM);
    cudaFuncSetAttribute(attn_mma_kernel, cudaFuncAttributeMaxDynamicSharedMemorySize, AT_SMEM);

    // gates (+ fused x->fp16)
    gate_kernel<<<PM / 4, 256>>>(x, fw, fb, wl, lf, xh);
    // weights -> transposed [N,K] fp16
    dim3 wt(64, 64, 4);
    wtrans_h<<<wt, 256>>>(Wq, Wk, Wv, Wo, wqh, wkh, wvh, woh);
    cumsum_kernel<<<PB * PH, 256>>>(lf, cf);
    // QKV GEMM (fp16 tensor cores, 128x128 tiles, 2 CTAs/SM); V written fp16
    dim3 gq(PHD / 128, PM / 128, 3);              // (16, 32, 3)
    hgemm_qkv<<<gq, 256, HG_SMEM>>>(xh, wqh, wkh, wvh, q, k, vh, PM, PHD, PC);
    // rope+rms -> fp16 (q pre-scaled by 1/sqrt(D))
    rope_rms_h<<<(PB * PT * PH) / 8, 256>>>(q, qh, cosp, sinp, 0.08838834764831845f);
    rope_rms_h<<<(PB * PT * PH) / 8, 256>>>(k, kh, cosp, sinp, 1.0f);
    // attention (all-fp16 mma, double-buffered K/V), writes fp16 Y
    dim3 ag(PT / 128, PH, PB);                    // (16, 16, 2)
    attn_mma_kernel<<<ag, 256, AT_SMEM>>>(qh, kh, vh, cf, yh, win);
    // Wo GEMM (fp16 in, fp32 out)
    dim3 gg(PC / 128, PM / 128);                  // (16, 32)
    hgemm<<<gg, 256, HG_SMEM>>>(yh, woh, out, PM, PC, PC);
}